// round 1
// baseline (speedup 1.0000x reference)
#include <cuda_runtime.h>

// FastLearnableEMA: y[b,t,c] = (sum_{s<=t} x[b,s,c] * w[s,c]) / max(a[c]^t, EPS)
//   a = clip(sigmoid(logit_alpha), 1e-4, 1-1e-4)
//   w[0] = 1 (a^0 * 1), w[s>0] = a^s * (1-a)
//
// One thread per (b,c): sequential scan over T with a^t maintained by
// recurrence. Adjacent threads = adjacent c -> fully coalesced 128B/warp
// accesses at every t step.

#define T_LEN 2048
#define C_LEN 512
#define CLAMP_LO 1e-4f
#define CLAMP_HI (1.0f - 1e-4f)
#define EMA_EPS 1e-8f
#define UNROLL 16

__global__ void __launch_bounds__(64) ema_scan_kernel(
    const float* __restrict__ x,
    const float* __restrict__ logit_alpha,
    float* __restrict__ y,
    int total)  // B * C
{
    int gid = blockIdx.x * blockDim.x + threadIdx.x;
    if (gid >= total) return;

    int b = gid / C_LEN;
    int c = gid - b * C_LEN;

    // a = clip(sigmoid(la), lo, hi)
    float la = logit_alpha[c];
    float a  = 1.0f / (1.0f + expf(-la));
    a = fminf(fmaxf(a, CLAMP_LO), CLAMP_HI);
    float oma = 1.0f - a;

    const float* xp = x + (size_t)b * (T_LEN * C_LEN) + c;
    float*       yp = y + (size_t)b * (T_LEN * C_LEN) + c;

    // t = 0: w = 1, divisor = max(1, eps) = 1
    float S = xp[0];
    yp[0] = S;
    float ap = a;  // a^t entering iteration t

    int t = 1;
    // Main unrolled body: batch UNROLL independent loads ahead of the
    // serial fma chain to keep ~UNROLL lines in flight per thread.
    for (; t + UNROLL <= T_LEN; t += UNROLL) {
        float xv[UNROLL];
        float yv[UNROLL];
        #pragma unroll
        for (int i = 0; i < UNROLL; i++)
            xv[i] = xp[(size_t)(t + i) * C_LEN];
        #pragma unroll
        for (int i = 0; i < UNROLL; i++) {
            S = fmaf(xv[i] * oma, ap, S);
            yv[i] = __fdividef(S, fmaxf(ap, EMA_EPS));
            ap *= a;
        }
        #pragma unroll
        for (int i = 0; i < UNROLL; i++)
            yp[(size_t)(t + i) * C_LEN] = yv[i];
    }
    // Tail (T-1 = 2047 = 127*16 + 15)
    for (; t < T_LEN; t++) {
        float xv = xp[(size_t)t * C_LEN];
        S = fmaf(xv * oma, ap, S);
        yp[(size_t)t * C_LEN] = __fdividef(S, fmaxf(ap, EMA_EPS));
        ap *= a;
    }
}

extern "C" void kernel_launch(void* const* d_in, const int* in_sizes, int n_in,
                              void* d_out, int out_size)
{
    const float* x  = (const float*)d_in[0];
    const float* la = (const float*)d_in[1];
    float*       y  = (float*)d_out;

    int B = in_sizes[0] / (T_LEN * C_LEN);   // 32
    int total = B * C_LEN;                   // 16384 scans

    int threads = 64;
    int blocks  = (total + threads - 1) / threads;  // 256 blocks
    ema_scan_kernel<<<blocks, threads>>>(x, la, y, total);
}

// round 6
// speedup vs baseline: 2.3582x; 2.3582x over previous
#include <cuda_runtime.h>

// FastLearnableEMA, chunk-parallel formulation.
//   a      = clip(sigmoid(logit_alpha), 1e-4, 1-1e-4)      [C]
//   u[t]   = x[t]*w[t],  w[0]=1, w[t>0]=(1-a)*a^t
//   y[t]   = cumsum_t(u) / max(a^t, eps)  =  cumsum_t(u) * min(a^-t, 1e8)
//
// The cumsum is a plain additive prefix sum -> split T into G chunks:
//   pass1: per-(b,c,g) chunk sums   -> g_partials
//   pass2: per-(b,c,g) base = sum of preceding partials, then local scan + write.
// Parallelism: B*C*G = 262144 threads (~55 warps/SM) instead of 16384.

#define T_LEN     2048
#define C_LEN     512
#define G_CHUNKS  16
#define L_CHUNK   (T_LEN / G_CHUNKS)   // 128
#define BC_MAX    (64 * C_LEN)         // supports B up to 64
#define CLAMP_LO  1e-4f
#define CLAMP_HI  (1.0f - 1e-4f)
#define INV_EPS   1e8f                 // 1/eps, eps = 1e-8

__device__ float g_partials[G_CHUNKS * BC_MAX];

__device__ __forceinline__ float clip_sigmoid(float la) {
    float a = 1.0f / (1.0f + expf(-la));
    return fminf(fmaxf(a, CLAMP_LO), CLAMP_HI);
}

// ---------------- Pass 1: chunk sums of u ----------------
#define U1 16
__global__ void __launch_bounds__(256) ema_pass1(
    const float* __restrict__ x,
    const float* __restrict__ logit_alpha,
    int BC)
{
    int gid = blockIdx.x * blockDim.x + threadIdx.x;   // = g*BC + bc
    if (gid >= BC * G_CHUNKS) return;
    int g  = gid / BC;
    int bc = gid - g * BC;
    int b  = bc / C_LEN;
    int c  = bc - b * C_LEN;

    float a   = clip_sigmoid(logit_alpha[c]);
    float oma = 1.0f - a;
    int   t0  = g * L_CHUNK;

    // a^t0 ; exact 1.0 for g==0
    float ap = (g == 0) ? 1.0f : exp2f((float)t0 * log2f(a));
    // weight multiplier for the first element of the chunk (t==0 uses 1, not oma)
    float w0 = (g == 0) ? 1.0f : oma;

    const float* xp = x + (size_t)b * (T_LEN * C_LEN) + (size_t)t0 * C_LEN + c;

    float S = 0.0f;
    for (int i = 0; i < L_CHUNK; i += U1) {
        float xv[U1];
        #pragma unroll
        for (int j = 0; j < U1; j++)
            xv[j] = xp[(size_t)(i + j) * C_LEN];
        #pragma unroll
        for (int j = 0; j < U1; j++) {
            float wm = (i + j == 0) ? w0 : oma;
            S = fmaf(xv[j] * wm, ap, S);
            ap *= a;
        }
    }
    g_partials[(size_t)g * BC + bc] = S;
}

// ---------------- Pass 2: base offset + local scan + write ----------------
#define U2 8
__global__ void __launch_bounds__(256) ema_pass2(
    const float* __restrict__ x,
    const float* __restrict__ logit_alpha,
    float* __restrict__ y,
    int BC)
{
    int gid = blockIdx.x * blockDim.x + threadIdx.x;   // = g*BC + bc
    if (gid >= BC * G_CHUNKS) return;
    int g  = gid / BC;
    int bc = gid - g * BC;
    int b  = bc / C_LEN;
    int c  = bc - b * C_LEN;

    float a     = clip_sigmoid(logit_alpha[c]);
    float oma   = 1.0f - a;
    float inv_a = 1.0f / a;
    int   t0    = g * L_CHUNK;

    float lg2a   = log2f(a);
    float ap     = (g == 0) ? 1.0f : exp2f((float)t0 * lg2a);
    float inv_ap = (g == 0) ? 1.0f : exp2f(-(float)t0 * lg2a);  // inf past ~t=840 -> clamped below
    float w0     = (g == 0) ? 1.0f : oma;

    // base = sum of all preceding chunk sums (coalesced, L2-resident)
    float base = 0.0f;
    for (int gg = 0; gg < g; gg++)
        base += g_partials[(size_t)gg * BC + bc];

    const float* xp = x + (size_t)b * (T_LEN * C_LEN) + (size_t)t0 * C_LEN + c;
    float*       yp = y + (size_t)b * (T_LEN * C_LEN) + (size_t)t0 * C_LEN + c;

    float S = base;
    for (int i = 0; i < L_CHUNK; i += U2) {
        float xv[U2];
        float yv[U2];
        #pragma unroll
        for (int j = 0; j < U2; j++)
            xv[j] = xp[(size_t)(i + j) * C_LEN];
        #pragma unroll
        for (int j = 0; j < U2; j++) {
            float wm = (i + j == 0) ? w0 : oma;
            S = fmaf(xv[j] * wm, ap, S);
            yv[j] = S * fminf(inv_ap, INV_EPS);   // = S / max(a^t, eps)
            ap     *= a;
            inv_ap *= inv_a;
        }
        #pragma unroll
        for (int j = 0; j < U2; j++)
            yp[(size_t)(i + j) * C_LEN] = yv[j];
    }
}

extern "C" void kernel_launch(void* const* d_in, const int* in_sizes, int n_in,
                              void* d_out, int out_size)
{
    const float* x  = (const float*)d_in[0];
    const float* la = (const float*)d_in[1];
    float*       y  = (float*)d_out;

    int B  = in_sizes[0] / (T_LEN * C_LEN);   // 32
    int BC = B * C_LEN;                        // 16384
    int total = BC * G_CHUNKS;                 // 262144

    int threads = 256;
    int blocks  = (total + threads - 1) / threads;  // 1024
    ema_pass1<<<blocks, threads>>>(x, la, BC);
    ema_pass2<<<blocks, threads>>>(x, la, y, BC);
}

// round 8
// speedup vs baseline: 3.2718x; 1.3874x over previous
#include <cuda_runtime.h>

// FastLearnableEMA — single-pass fused kernel.
//   a    = clip(sigmoid(logit_alpha), 1e-4, 1-1e-4)             [C]
//   u[t] = x[t]*w[t],  w[0]=1, w[t>0]=(1-a)*a^t
//   y[t] = cumsum_t(u) * min(a^-t, 1e8)     (== cumsum / max(a^t, 1e-8))
//
// Block = (batch b, 32-channel tile, full T). T is walked in 8 tiles of 256;
// within a tile, warp w owns a 32-t chunk (one channel per lane), held in
// registers. Cross-chunk prefix = smem exclusive scan over the 8 warp
// partials + a running base carried across tiles. x is read exactly once,
// y written exactly once: 256 MB total HBM traffic.

#define T_LEN   2048
#define C_LEN   512
#define CT      32                 // channels per block
#define WARPS   8
#define LT      32                 // t per thread per tile
#define TILE_T  (WARPS * LT)       // 256
#define NTILES  (T_LEN / TILE_T)   // 8
#define CLAMP_LO 1e-4f
#define CLAMP_HI (1.0f - 1e-4f)
#define INV_EPS  1e8f              // 1/eps

__global__ void __launch_bounds__(256) ema_fused(
    const float* __restrict__ x,
    const float* __restrict__ logit_alpha,
    float* __restrict__ y)
{
    const int warp = threadIdx.x >> 5;
    const int lane = threadIdx.x & 31;
    const int b    = blockIdx.x >> 4;                 // C/CT = 16 tiles per b
    const int c    = ((blockIdx.x & 15) * CT) + lane;

    __shared__ float sm_part[WARPS][CT];
    __shared__ float sm_base[CT];

    // per-channel constants
    float la  = logit_alpha[c];
    float a   = 1.0f / (1.0f + expf(-la));
    a = fminf(fmaxf(a, CLAMP_LO), CLAMP_HI);
    const float oma   = 1.0f - a;
    const float inv_a = 1.0f / a;
    const float lg2a  = log2f(a);

    // a^256 and a^-256 by repeated squaring (tile stride)
    float a256 = a;
    #pragma unroll
    for (int i = 0; i < 8; i++) a256 *= a256;         // a^256 (may underflow->0, matches ref)
    float ia256 = inv_a;
    #pragma unroll
    for (int i = 0; i < 8; i++) ia256 *= ia256;       // a^-256 (may overflow->inf, clamped later)

    // per-thread chunk-start powers at t = warp*LT (exact 1.0 for warp 0)
    const float t0w   = (float)(warp * LT);
    float ap     = (warp == 0) ? 1.0f : exp2f(t0w * lg2a);
    float inv_ap = (warp == 0) ? 1.0f : exp2f(-t0w * lg2a);

    if (threadIdx.x < CT) sm_base[threadIdx.x] = 0.0f;
    __syncthreads();

    const size_t row = (size_t)b * T_LEN * C_LEN + c;

    for (int tile = 0; tile < NTILES; tile++) {
        const int tbase = tile * TILE_T + warp * LT;
        const float* xp = x + row + (size_t)tbase * C_LEN;
        float*       yp = y + row + (size_t)tbase * C_LEN;

        // ---- load this thread's 32-t chunk (fully coalesced: 128B/warp/row)
        float v[LT];
        #pragma unroll
        for (int i = 0; i < LT; i++)
            v[i] = xp[(size_t)i * C_LEN];

        // ---- chunk sum of u
        const bool has_t0 = (tbase == 0);             // only tile 0 / warp 0
        float ap_i = ap;
        float S = 0.0f;
        #pragma unroll
        for (int i = 0; i < LT; i++) {
            float wm = (has_t0 && i == 0) ? 1.0f : oma;
            S = fmaf(v[i] * wm, ap_i, S);
            ap_i *= a;
        }
        sm_part[warp][lane] = S;
        __syncthreads();

        // ---- exclusive prefix across warps + running base
        float base = sm_base[lane];
        #pragma unroll
        for (int w = 0; w < WARPS - 1; w++)
            if (w < warp) base += sm_part[w][lane];
        __syncthreads();
        if (warp == WARPS - 1)
            sm_base[lane] = base + S;                 // new running total

        // ---- local scan, y written in place of x registers
        float Sc    = base;
        float ap_j  = ap;
        float iap_j = inv_ap;
        #pragma unroll
        for (int i = 0; i < LT; i++) {
            float wm = (has_t0 && i == 0) ? 1.0f : oma;
            Sc = fmaf(v[i] * wm, ap_j, Sc);
            v[i] = Sc * fminf(iap_j, INV_EPS);        // = Sc / max(a^t, eps)
            ap_j  *= a;
            iap_j *= inv_a;
        }
        #pragma unroll
        for (int i = 0; i < LT; i++)
            yp[(size_t)i * C_LEN] = v[i];

        // advance chunk-start powers by one tile (256 t)
        ap     *= a256;
        inv_ap *= ia256;
    }
}

extern "C" void kernel_launch(void* const* d_in, const int* in_sizes, int n_in,
                              void* d_out, int out_size)
{
    const float* x  = (const float*)d_in[0];
    const float* la = (const float*)d_in[1];
    float*       y  = (float*)d_out;

    int B = in_sizes[0] / (T_LEN * C_LEN);        // 32
    int blocks = B * (C_LEN / CT);                // 512
    ema_fused<<<blocks, 256>>>(x, la, y);
}

// round 9
// speedup vs baseline: 3.5742x; 1.0924x over previous
#include <cuda_runtime.h>

// FastLearnableEMA — single-pass fused kernel (round 9: occupancy + wave fix).
//   a    = clip(sigmoid(logit_alpha), 1e-4, 1-1e-4)             [C]
//   u[t] = x[t]*w[t],  w[0]=1, w[t>0]=(1-a)*a^t
//   y[t] = cumsum_t(u) * min(a^-t, 1e8)     (== cumsum / max(a^t, 1e-8))
//
// Block = (batch b, 32-channel tile, full T). T walked in 16 tiles of 128 t;
// warp w owns a 16-t chunk per tile (one channel per lane) in registers.
// Cross-chunk prefix via double-buffered smem (ONE barrier per tile).
// x read once, y written once: 256 MB HBM traffic total.
// LT=16 keeps regs < 64 -> 4 CTAs/SM -> all 512 CTAs in one wave.

#define T_LEN   2048
#define C_LEN   512
#define CT      32                 // channels per block
#define WARPS   8
#define LT      16                 // t per thread per tile
#define TILE_T  (WARPS * LT)       // 128
#define NTILES  (T_LEN / TILE_T)   // 16
#define CLAMP_LO 1e-4f
#define CLAMP_HI (1.0f - 1e-4f)
#define INV_EPS  1e8f              // 1/eps

__global__ void __launch_bounds__(256, 4) ema_fused(
    const float* __restrict__ x,
    const float* __restrict__ logit_alpha,
    float* __restrict__ y)
{
    const int warp = threadIdx.x >> 5;
    const int lane = threadIdx.x & 31;
    const int b    = blockIdx.x >> 4;                 // C/CT = 16 tiles per b
    const int c    = ((blockIdx.x & 15) * CT) + lane;

    __shared__ float sm_part[2][WARPS][CT];
    __shared__ float sm_base[2][CT];

    // per-channel constants
    float la  = logit_alpha[c];
    float a   = 1.0f / (1.0f + expf(-la));
    a = fminf(fmaxf(a, CLAMP_LO), CLAMP_HI);
    const float oma   = 1.0f - a;
    const float inv_a = 1.0f / a;
    const float lg2a  = log2f(a);

    // a^TILE_T and a^-TILE_T by repeated squaring (tile stride = 128 = 2^7)
    float aT = a;
    #pragma unroll
    for (int i = 0; i < 7; i++) aT *= aT;             // a^128 (underflow->0 ok)
    float iaT = inv_a;
    #pragma unroll
    for (int i = 0; i < 7; i++) iaT *= iaT;           // a^-128 (overflow->inf, clamped later)

    // per-thread chunk-start powers at t = warp*LT (exact 1.0 for warp 0)
    const float t0w   = (float)(warp * LT);
    float ap     = (warp == 0) ? 1.0f : exp2f(t0w * lg2a);
    float inv_ap = (warp == 0) ? 1.0f : exp2f(-t0w * lg2a);

    if (threadIdx.x < CT) sm_base[0][threadIdx.x] = 0.0f;
    // visibility of this init is ordered by the first tile's __syncthreads()

    const size_t row = (size_t)b * T_LEN * C_LEN + c;

    #pragma unroll 1
    for (int tile = 0; tile < NTILES; tile++) {
        const int p     = tile & 1;
        const int tbase = tile * TILE_T + warp * LT;
        const float* xp = x + row + (size_t)tbase * C_LEN;
        float*       yp = y + row + (size_t)tbase * C_LEN;

        // ---- load this thread's 16-t chunk (coalesced: 128B/warp/row)
        float v[LT];
        #pragma unroll
        for (int i = 0; i < LT; i++)
            v[i] = xp[(size_t)i * C_LEN];

        // ---- chunk sum of u
        const bool has_t0 = (tbase == 0);             // only tile 0 / warp 0
        float ap_i = ap;
        float S = 0.0f;
        #pragma unroll
        for (int i = 0; i < LT; i++) {
            float wm = (has_t0 && i == 0) ? 1.0f : oma;
            S = fmaf(v[i] * wm, ap_i, S);
            ap_i *= a;
        }
        sm_part[p][warp][lane] = S;
        __syncthreads();   // orders: sm_part[p] writes, and prev tile's sm_base[p] write

        // ---- exclusive prefix across warps + running base (double-buffered)
        float base = sm_base[p][lane];
        #pragma unroll
        for (int w = 0; w < WARPS - 1; w++)
            if (w < warp) base += sm_part[p][w][lane];
        if (warp == WARPS - 1)
            sm_base[p ^ 1][lane] = base + S;          // next tile's running total

        // ---- local scan; reuse v[] for y
        float Sc    = base;
        float ap_j  = ap;
        float iap_j = inv_ap;
        #pragma unroll
        for (int i = 0; i < LT; i++) {
            float wm = (has_t0 && i == 0) ? 1.0f : oma;
            Sc = fmaf(v[i] * wm, ap_j, Sc);
            v[i] = Sc * fminf(iap_j, INV_EPS);        // = Sc / max(a^t, eps)
            ap_j  *= a;
            iap_j *= inv_a;
        }
        #pragma unroll
        for (int i = 0; i < LT; i++)
            yp[(size_t)i * C_LEN] = v[i];

        // advance chunk-start powers by one tile (128 t)
        ap     *= aT;
        inv_ap *= iaT;
    }
}

extern "C" void kernel_launch(void* const* d_in, const int* in_sizes, int n_in,
                              void* d_out, int out_size)
{
    const float* x  = (const float*)d_in[0];
    const float* la = (const float*)d_in[1];
    float*       y  = (float*)d_out;

    int B = in_sizes[0] / (T_LEN * C_LEN);        // 32
    int blocks = B * (C_LEN / CT);                // 512
    ema_fused<<<blocks, 256>>>(x, la, y);
}